// round 7
// baseline (speedup 1.0000x reference)
#include <cuda_runtime.h>

// Problem constants (fixed-shape problem)
#define WIN   48
#define DIN   64
#define DOUT  128
#define BATCH 4096
#define NSEG  (BATCH * WIN)      // 196608 segments
#define NEV_MAX 2000000
#define SCAN_BLK 2048            // elems per scan block
#define SCAN_NBLK (NSEG / SCAN_BLK)   // 96

// Scratch
__device__ int   g_cnt[NSEG];            // events per segment
__device__ int   g_cur[NSEG];            // exclusive offsets (then cursors -> end)
__device__ int   g_part[SCAN_NBLK];      // scan partials (block totals)
__device__ int   g_bucket[NEV_MAX];      // event ids grouped by segment
__device__ float g_mean[NSEG * DIN];     // segment means (written, never atomically)

// ---------------------------------------------------------------------------
// 1) zero counters
// ---------------------------------------------------------------------------
__global__ void zero_cnt_kernel() {
    int i = blockIdx.x * blockDim.x + threadIdx.x;
    if (i < NSEG) g_cnt[i] = 0;
}

// ---------------------------------------------------------------------------
// 2) histogram: events per segment (4 events per thread, int4 loads)
// ---------------------------------------------------------------------------
__global__ void hist_kernel(const int* __restrict__ bi,
                            const int* __restrict__ wi, int n) {
    int t = blockIdx.x * blockDim.x + threadIdx.x;
    int i4 = t * 4;
    if (i4 + 3 < n) {
        int4 b = *reinterpret_cast<const int4*>(bi + i4);
        int4 w = *reinterpret_cast<const int4*>(wi + i4);
        atomicAdd(&g_cnt[b.x * WIN + w.x], 1);
        atomicAdd(&g_cnt[b.y * WIN + w.y], 1);
        atomicAdd(&g_cnt[b.z * WIN + w.z], 1);
        atomicAdd(&g_cnt[b.w * WIN + w.w], 1);
    } else {
        for (int i = i4; i < n; i++)
            atomicAdd(&g_cnt[bi[i] * WIN + wi[i]], 1);
    }
}

// ---------------------------------------------------------------------------
// 3a) per-2048-block exclusive scan; block totals -> g_part
// ---------------------------------------------------------------------------
__global__ __launch_bounds__(1024) void scan_a_kernel() {
    __shared__ int warp_tot[32];
    int tid = threadIdx.x;
    int base = blockIdx.x * SCAN_BLK;
    int a = g_cnt[base + 2 * tid];
    int b = g_cnt[base + 2 * tid + 1];
    int s = a + b;
    int lane = tid & 31, wid = tid >> 5;
    int v = s;
    #pragma unroll
    for (int o = 1; o < 32; o <<= 1) {
        int t = __shfl_up_sync(0xffffffffu, v, o);
        if (lane >= o) v += t;
    }
    if (lane == 31) warp_tot[wid] = v;
    __syncthreads();
    if (wid == 0) {
        int w = warp_tot[lane];
        #pragma unroll
        for (int o = 1; o < 32; o <<= 1) {
            int t = __shfl_up_sync(0xffffffffu, w, o);
            if (lane >= o) w += t;
        }
        warp_tot[lane] = w;   // inclusive warp totals
    }
    __syncthreads();
    int warp_off = (wid == 0) ? 0 : warp_tot[wid - 1];
    int incl = v + warp_off;              // inclusive over block (this pair)
    g_cur[base + 2 * tid]     = incl - s; // exclusive for a
    g_cur[base + 2 * tid + 1] = incl - b; // exclusive for b
    if (tid == 1023) g_part[blockIdx.x] = incl;
}

// ---------------------------------------------------------------------------
// 3b) add global prefix: each 256-block computes sum of g_part[0..sb) itself
// ---------------------------------------------------------------------------
__global__ __launch_bounds__(256) void scan_c_kernel() {
    __shared__ int s_off;
    int blk = blockIdx.x;
    int sb = blk >> 3;                // which 2048-scan-block we belong to
    if (threadIdx.x < 32) {
        int acc = 0;
        for (int i = threadIdx.x; i < sb; i += 32) acc += g_part[i];
        #pragma unroll
        for (int o = 16; o > 0; o >>= 1)
            acc += __shfl_down_sync(0xffffffffu, acc, o);
        if (threadIdx.x == 0) s_off = acc;
    }
    __syncthreads();
    g_cur[blk * 256 + threadIdx.x] += s_off;
}

// ---------------------------------------------------------------------------
// 4) scatter event indices into buckets (4 events per thread)
// ---------------------------------------------------------------------------
__global__ void scatter_idx_kernel(const int* __restrict__ bi,
                                   const int* __restrict__ wi, int n) {
    int t = blockIdx.x * blockDim.x + threadIdx.x;
    int i4 = t * 4;
    if (i4 + 3 < n) {
        int4 b = *reinterpret_cast<const int4*>(bi + i4);
        int4 w = *reinterpret_cast<const int4*>(wi + i4);
        int p0 = atomicAdd(&g_cur[b.x * WIN + w.x], 1);
        int p1 = atomicAdd(&g_cur[b.y * WIN + w.y], 1);
        int p2 = atomicAdd(&g_cur[b.z * WIN + w.z], 1);
        int p3 = atomicAdd(&g_cur[b.w * WIN + w.w], 1);
        g_bucket[p0] = i4;
        g_bucket[p1] = i4 + 1;
        g_bucket[p2] = i4 + 2;
        g_bucket[p3] = i4 + 3;
    } else {
        for (int i = i4; i < n; i++) {
            int pos = atomicAdd(&g_cur[bi[i] * WIN + wi[i]], 1);
            g_bucket[pos] = i;
        }
    }
}

// ---------------------------------------------------------------------------
// 5) gather-reduce: TWO warps per segment (warp-half h covers dims
//    [32h, 32h+32)), unroll-8, no atomics. 393K warps for latency hiding.
//    Writes MEANS directly; empty segments write zeros.
// ---------------------------------------------------------------------------
__global__ __launch_bounds__(256) void reduce_kernel(const float* __restrict__ in) {
    int gw   = blockIdx.x * 8 + (threadIdx.x >> 5);  // global warp id
    int seg  = gw >> 1;
    int half = gw & 1;
    int lane = threadIdx.x & 31;
    if (seg >= NSEG) return;

    int cnt   = __ldg(&g_cnt[seg]);
    int end   = __ldg(&g_cur[seg]);   // after scatter, cur == start + cnt
    int start = end - cnt;

    const float* base = in + half * 32 + lane;   // this warp's 128B column

    float a = 0.f;
    int i = start;
    for (; i + 7 < end; i += 8) {
        int e0 = __ldg(&g_bucket[i]);
        int e1 = __ldg(&g_bucket[i + 1]);
        int e2 = __ldg(&g_bucket[i + 2]);
        int e3 = __ldg(&g_bucket[i + 3]);
        int e4 = __ldg(&g_bucket[i + 4]);
        int e5 = __ldg(&g_bucket[i + 5]);
        int e6 = __ldg(&g_bucket[i + 6]);
        int e7 = __ldg(&g_bucket[i + 7]);
        float x0 = __ldcs(base + (size_t)e0 * DIN);
        float x1 = __ldcs(base + (size_t)e1 * DIN);
        float x2 = __ldcs(base + (size_t)e2 * DIN);
        float x3 = __ldcs(base + (size_t)e3 * DIN);
        float x4 = __ldcs(base + (size_t)e4 * DIN);
        float x5 = __ldcs(base + (size_t)e5 * DIN);
        float x6 = __ldcs(base + (size_t)e6 * DIN);
        float x7 = __ldcs(base + (size_t)e7 * DIN);
        a += ((x0 + x1) + (x2 + x3)) + ((x4 + x5) + (x6 + x7));
    }
    if (i + 3 < end) {
        int e0 = __ldg(&g_bucket[i]);
        int e1 = __ldg(&g_bucket[i + 1]);
        int e2 = __ldg(&g_bucket[i + 2]);
        int e3 = __ldg(&g_bucket[i + 3]);
        float x0 = __ldcs(base + (size_t)e0 * DIN);
        float x1 = __ldcs(base + (size_t)e1 * DIN);
        float x2 = __ldcs(base + (size_t)e2 * DIN);
        float x3 = __ldcs(base + (size_t)e3 * DIN);
        a += (x0 + x1) + (x2 + x3);
        i += 4;
    }
    for (; i < end; i++) {
        int e = __ldg(&g_bucket[i]);
        a += __ldcs(base + (size_t)e * DIN);
    }
    float inv = (cnt > 0) ? (1.f / (float)cnt) : 0.f;
    g_mean[(size_t)seg * DIN + half * 32 + lane] = a * inv;
}

// ---------------------------------------------------------------------------
// 6) per-batch fused  GEMM(means @ W) -> +bias(if nonempty) -> permute
// ---------------------------------------------------------------------------
__device__ __forceinline__ void unpack2(unsigned long long v, float& lo, float& hi) {
    asm("mov.b64 {%0, %1}, %2;" : "=f"(lo), "=f"(hi) : "l"(v));
}
__device__ __forceinline__ void fma2(unsigned long long& acc, float m,
                                     unsigned long long w) {
    unsigned long long mm;
    asm("mov.b64 %0, {%1, %1};" : "=l"(mm) : "f"(m));
    asm("fma.rn.f32x2 %0, %1, %2, %0;" : "+l"(acc) : "l"(mm), "l"(w));
}

__global__ __launch_bounds__(256) void pool_gemm_kernel(
    const float* __restrict__ Wm,     // [DIN][DOUT] row-major (k-major)
    const float* __restrict__ bias,   // [DOUT]
    float*       __restrict__ out)    // [BATCH][DOUT][WIN]
{
    __shared__ float s_mean[WIN * DIN];   // 3072 floats
    __shared__ float s_w[DIN * DOUT];     // 8192 floats; reused as out[128][49]
    __shared__ float s_b[DOUT];
    __shared__ float s_has[WIN];

    int b   = blockIdx.x;
    int tid = threadIdx.x;

    if (tid < WIN) s_has[tid] = (g_cnt[b * WIN + tid] > 0) ? 1.f : 0.f;
    if (tid < DOUT) s_b[tid] = bias[tid];

    // ---- load W (coalesced float4) ----
    {
        const float4* w4 = reinterpret_cast<const float4*>(Wm);
        float4* sw4 = reinterpret_cast<float4*>(s_w);
        #pragma unroll
        for (int i = tid; i < DIN * DOUT / 4; i += 256) sw4[i] = w4[i];
    }

    // ---- load means (already divided) ----
    {
        const float4* srow = reinterpret_cast<const float4*>(
            g_mean + (size_t)b * WIN * DIN);
        float4* sm4 = reinterpret_cast<float4*>(s_mean);
        #pragma unroll
        for (int i = tid; i < WIN * DIN / 4; i += 256) sm4[i] = srow[i];
    }
    __syncthreads();   // means + W ready

    // ---- compute 6w x 4d tile per thread ----
    int dg = tid & 31;
    int wg = tid >> 5;
    int d0 = dg * 2;

    unsigned long long acc0[6], acc1[6];
    #pragma unroll
    for (int i = 0; i < 6; i++) { acc0[i] = 0ull; acc1[i] = 0ull; }

    const float* mbase = s_mean + wg * 6 * DIN;

    #pragma unroll
    for (int kk = 0; kk < 16; kk++) {
        int k = kk * 4;
        float4 m[6];
        #pragma unroll
        for (int i = 0; i < 6; i++)
            m[i] = *reinterpret_cast<const float4*>(mbase + i * DIN + k);
        #pragma unroll
        for (int j = 0; j < 4; j++) {
            unsigned long long w0 = *reinterpret_cast<const unsigned long long*>(
                s_w + (k + j) * DOUT + d0);
            unsigned long long w1 = *reinterpret_cast<const unsigned long long*>(
                s_w + (k + j) * DOUT + 64 + d0);
            #pragma unroll
            for (int i = 0; i < 6; i++) {
                float mv = (j == 0) ? m[i].x : (j == 1) ? m[i].y
                         : (j == 2) ? m[i].z : m[i].w;
                fma2(acc0[i], mv, w0);
                fma2(acc1[i], mv, w1);
            }
        }
    }

    __syncthreads();   // everyone done reading s_w; reuse as out staging

    // ---- stage results as out[d][w] pad-49 (+bias if nonempty) ----
    float b0x = s_b[d0],      b0y = s_b[d0 + 1];
    float b1x = s_b[d0 + 64], b1y = s_b[d0 + 65];
    #pragma unroll
    for (int i = 0; i < 6; i++) {
        int w = wg * 6 + i;
        float has = s_has[w];
        float a0x, a0y, a1x, a1y;
        unpack2(acc0[i], a0x, a0y);
        unpack2(acc1[i], a1x, a1y);
        s_w[(d0    ) * 49 + w] = a0x + has * b0x;
        s_w[(d0 + 1) * 49 + w] = a0y + has * b0y;
        s_w[(d0 + 64) * 49 + w] = a1x + has * b1x;
        s_w[(d0 + 65) * 49 + w] = a1y + has * b1y;
    }
    __syncthreads();

    // ---- coalesced float4 store of out[b][d][w] ----
    float* obase = out + (size_t)b * DOUT * WIN;
    #pragma unroll
    for (int it = 0; it < 6; it++) {
        int j = it * 1024 + tid * 4;   // 48 % 4 == 0 -> all 4 elems share d
        int d = j / 48;
        int w = j - d * 48;
        const float* src = s_w + d * 49 + w;
        float4 v = make_float4(src[0], src[1], src[2], src[3]);
        *reinterpret_cast<float4*>(obase + j) = v;
    }
}

// ---------------------------------------------------------------------------
extern "C" void kernel_launch(void* const* d_in, const int* in_sizes, int n_in,
                              void* d_out, int out_size) {
    const float* input = (const float*)d_in[0];
    const float* Wm    = (const float*)d_in[1];
    const float* bias  = (const float*)d_in[2];

    const int* bi;
    const int* wi;
    int n_events;
    if (n_in >= 6 && in_sizes[3] == 1) {
        bi = (const int*)d_in[4];
        wi = (const int*)d_in[5];
        n_events = in_sizes[4];
    } else {
        bi = (const int*)d_in[3];
        wi = (const int*)d_in[4];
        n_events = in_sizes[3];
    }

    int eb4 = (n_events + 4 * 256 - 1) / (4 * 256);   // 4 events per thread

    zero_cnt_kernel<<<(NSEG + 255) / 256, 256>>>();
    hist_kernel<<<eb4, 256>>>(bi, wi, n_events);
    scan_a_kernel<<<SCAN_NBLK, 1024>>>();
    scan_c_kernel<<<NSEG / 256, 256>>>();
    scatter_idx_kernel<<<eb4, 256>>>(bi, wi, n_events);
    reduce_kernel<<<NSEG * 2 / 8, 256>>>(input);   // 2 warps per segment
    pool_gemm_kernel<<<BATCH, 256>>>(Wm, bias, (float*)d_out);
}

// round 8
// speedup vs baseline: 1.1523x; 1.1523x over previous
#include <cuda_runtime.h>

// Problem constants (fixed-shape problem)
#define WIN   48
#define DIN   64
#define DOUT  128
#define BATCH 4096
#define NSEG  (BATCH * WIN)      // 196608 segments
#define NEV_MAX 2000000
#define SCAN_BLK 2048            // elems per scan block
#define SCAN_NBLK (NSEG / SCAN_BLK)   // 96

// Scratch
__device__ int   g_cnt[NSEG];            // events per segment
__device__ int   g_cur[NSEG];            // exclusive offsets (then cursors -> end)
__device__ int   g_part[SCAN_NBLK];      // scan partials (block totals)
__device__ int   g_bucket[NEV_MAX];      // event ids grouped by segment
__device__ float g_mean[NSEG * DIN];     // segment means (written, never atomically)

// ---------------------------------------------------------------------------
// 1) zero counters
// ---------------------------------------------------------------------------
__global__ void zero_cnt_kernel() {
    int i = blockIdx.x * blockDim.x + threadIdx.x;
    if (i < NSEG) g_cnt[i] = 0;
}

// ---------------------------------------------------------------------------
// 2) histogram: events per segment
// ---------------------------------------------------------------------------
__global__ void hist_kernel(const int* __restrict__ bi,
                            const int* __restrict__ wi, int n) {
    int i = blockIdx.x * blockDim.x + threadIdx.x;
    if (i >= n) return;
    int seg = bi[i] * WIN + wi[i];
    atomicAdd(&g_cnt[seg], 1);
}

// ---------------------------------------------------------------------------
// 3a) per-2048-block exclusive scan; block totals -> g_part
// ---------------------------------------------------------------------------
__global__ __launch_bounds__(1024) void scan_a_kernel() {
    __shared__ int warp_tot[32];
    int tid = threadIdx.x;
    int base = blockIdx.x * SCAN_BLK;
    int a = g_cnt[base + 2 * tid];
    int b = g_cnt[base + 2 * tid + 1];
    int s = a + b;
    int lane = tid & 31, wid = tid >> 5;
    int v = s;
    #pragma unroll
    for (int o = 1; o < 32; o <<= 1) {
        int t = __shfl_up_sync(0xffffffffu, v, o);
        if (lane >= o) v += t;
    }
    if (lane == 31) warp_tot[wid] = v;
    __syncthreads();
    if (wid == 0) {
        int w = warp_tot[lane];
        #pragma unroll
        for (int o = 1; o < 32; o <<= 1) {
            int t = __shfl_up_sync(0xffffffffu, w, o);
            if (lane >= o) w += t;
        }
        warp_tot[lane] = w;   // inclusive warp totals
    }
    __syncthreads();
    int warp_off = (wid == 0) ? 0 : warp_tot[wid - 1];
    int incl = v + warp_off;              // inclusive over block (this pair)
    g_cur[base + 2 * tid]     = incl - s; // exclusive for a
    g_cur[base + 2 * tid + 1] = incl - b; // exclusive for b
    if (tid == 1023) g_part[blockIdx.x] = incl;
}

// ---------------------------------------------------------------------------
// 3b) add global prefix: each 256-block computes sum of g_part[0..sb) itself
// ---------------------------------------------------------------------------
__global__ __launch_bounds__(256) void scan_c_kernel() {
    __shared__ int s_off;
    int blk = blockIdx.x;
    int sb = blk >> 3;                // which 2048-scan-block we belong to
    if (threadIdx.x < 32) {
        int acc = 0;
        for (int i = threadIdx.x; i < sb; i += 32) acc += g_part[i];
        #pragma unroll
        for (int o = 16; o > 0; o >>= 1)
            acc += __shfl_down_sync(0xffffffffu, acc, o);
        if (threadIdx.x == 0) s_off = acc;
    }
    __syncthreads();
    g_cur[blk * 256 + threadIdx.x] += s_off;
}

// ---------------------------------------------------------------------------
// 4) scatter event indices into buckets (g_cur becomes END offset)
// ---------------------------------------------------------------------------
__global__ void scatter_idx_kernel(const int* __restrict__ bi,
                                   const int* __restrict__ wi, int n) {
    int i = blockIdx.x * blockDim.x + threadIdx.x;
    if (i >= n) return;
    int seg = bi[i] * WIN + wi[i];
    int pos = atomicAdd(&g_cur[seg], 1);
    g_bucket[pos] = i;
}

// ---------------------------------------------------------------------------
// 5) gather-reduce: ONE warp per segment, fully-predicated unroll-4 loop
//    (clamped indices + SEL masking -> no serial remainder tail).
//    Writes MEANS directly; empty segments write zeros.
// ---------------------------------------------------------------------------
__global__ __launch_bounds__(256) void reduce_kernel(const float* __restrict__ in) {
    int seg  = (blockIdx.x * blockDim.x + threadIdx.x) >> 5;
    int lane = threadIdx.x & 31;
    if (seg >= NSEG) return;

    int cnt   = __ldg(&g_cnt[seg]);
    int end   = __ldg(&g_cur[seg]);   // after scatter, cur == start + cnt
    int start = end - cnt;
    int last  = end - 1;              // only used when cnt > 0

    float a0 = 0.f, a1 = 0.f;
    for (int i = start; i < end; i += 4) {
        // clamped indices: always in-bounds, masked after load
        int j1 = i + 1 < end ? i + 1 : last;
        int j2 = i + 2 < end ? i + 2 : last;
        int j3 = i + 3 < end ? i + 3 : last;
        int e0 = __ldg(&g_bucket[i]);
        int e1 = __ldg(&g_bucket[j1]);
        int e2 = __ldg(&g_bucket[j2]);
        int e3 = __ldg(&g_bucket[j3]);
        const float* r0 = in + (size_t)e0 * DIN + lane;
        const float* r1 = in + (size_t)e1 * DIN + lane;
        const float* r2 = in + (size_t)e2 * DIN + lane;
        const float* r3 = in + (size_t)e3 * DIN + lane;
        float x0 = __ldcs(r0);
        float x1 = __ldcs(r0 + 32);
        float y0 = __ldcs(r1);
        float y1 = __ldcs(r1 + 32);
        float z0 = __ldcs(r2);
        float z1 = __ldcs(r2 + 32);
        float w0 = __ldcs(r3);
        float w1 = __ldcs(r3 + 32);
        // mask duplicated tail entries (SEL, no branches)
        if (i + 1 >= end) { y0 = 0.f; y1 = 0.f; }
        if (i + 2 >= end) { z0 = 0.f; z1 = 0.f; }
        if (i + 3 >= end) { w0 = 0.f; w1 = 0.f; }
        a0 += (x0 + y0) + (z0 + w0);
        a1 += (x1 + y1) + (z1 + w1);
    }
    float inv = (cnt > 0) ? (1.f / (float)cnt) : 0.f;
    g_mean[(size_t)seg * DIN + lane]      = a0 * inv;
    g_mean[(size_t)seg * DIN + lane + 32] = a1 * inv;
}

// ---------------------------------------------------------------------------
// 6) per-batch fused  GEMM(means @ W) -> +bias(if nonempty) -> permute
// ---------------------------------------------------------------------------
__device__ __forceinline__ void unpack2(unsigned long long v, float& lo, float& hi) {
    asm("mov.b64 {%0, %1}, %2;" : "=f"(lo), "=f"(hi) : "l"(v));
}
__device__ __forceinline__ void fma2(unsigned long long& acc, float m,
                                     unsigned long long w) {
    unsigned long long mm;
    asm("mov.b64 %0, {%1, %1};" : "=l"(mm) : "f"(m));
    asm("fma.rn.f32x2 %0, %1, %2, %0;" : "+l"(acc) : "l"(mm), "l"(w));
}

__global__ __launch_bounds__(256) void pool_gemm_kernel(
    const float* __restrict__ Wm,     // [DIN][DOUT] row-major (k-major)
    const float* __restrict__ bias,   // [DOUT]
    float*       __restrict__ out)    // [BATCH][DOUT][WIN]
{
    __shared__ float s_mean[WIN * DIN];   // 3072 floats
    __shared__ float s_w[DIN * DOUT];     // 8192 floats; reused as out[128][49]
    __shared__ float s_b[DOUT];
    __shared__ float s_has[WIN];

    int b   = blockIdx.x;
    int tid = threadIdx.x;

    if (tid < WIN) s_has[tid] = (g_cnt[b * WIN + tid] > 0) ? 1.f : 0.f;
    if (tid < DOUT) s_b[tid] = bias[tid];

    // ---- load W (coalesced float4) ----
    {
        const float4* w4 = reinterpret_cast<const float4*>(Wm);
        float4* sw4 = reinterpret_cast<float4*>(s_w);
        #pragma unroll
        for (int i = tid; i < DIN * DOUT / 4; i += 256) sw4[i] = w4[i];
    }

    // ---- load means (already divided) ----
    {
        const float4* srow = reinterpret_cast<const float4*>(
            g_mean + (size_t)b * WIN * DIN);
        float4* sm4 = reinterpret_cast<float4*>(s_mean);
        #pragma unroll
        for (int i = tid; i < WIN * DIN / 4; i += 256) sm4[i] = srow[i];
    }
    __syncthreads();   // means + W ready

    // ---- compute 6w x 4d tile per thread ----
    int dg = tid & 31;
    int wg = tid >> 5;
    int d0 = dg * 2;

    unsigned long long acc0[6], acc1[6];
    #pragma unroll
    for (int i = 0; i < 6; i++) { acc0[i] = 0ull; acc1[i] = 0ull; }

    const float* mbase = s_mean + wg * 6 * DIN;

    #pragma unroll
    for (int kk = 0; kk < 16; kk++) {
        int k = kk * 4;
        float4 m[6];
        #pragma unroll
        for (int i = 0; i < 6; i++)
            m[i] = *reinterpret_cast<const float4*>(mbase + i * DIN + k);
        #pragma unroll
        for (int j = 0; j < 4; j++) {
            unsigned long long w0 = *reinterpret_cast<const unsigned long long*>(
                s_w + (k + j) * DOUT + d0);
            unsigned long long w1 = *reinterpret_cast<const unsigned long long*>(
                s_w + (k + j) * DOUT + 64 + d0);
            #pragma unroll
            for (int i = 0; i < 6; i++) {
                float mv = (j == 0) ? m[i].x : (j == 1) ? m[i].y
                         : (j == 2) ? m[i].z : m[i].w;
                fma2(acc0[i], mv, w0);
                fma2(acc1[i], mv, w1);
            }
        }
    }

    __syncthreads();   // everyone done reading s_w; reuse as out staging

    // ---- stage results as out[d][w] pad-49 (+bias if nonempty) ----
    float b0x = s_b[d0],      b0y = s_b[d0 + 1];
    float b1x = s_b[d0 + 64], b1y = s_b[d0 + 65];
    #pragma unroll
    for (int i = 0; i < 6; i++) {
        int w = wg * 6 + i;
        float has = s_has[w];
        float a0x, a0y, a1x, a1y;
        unpack2(acc0[i], a0x, a0y);
        unpack2(acc1[i], a1x, a1y);
        s_w[(d0    ) * 49 + w] = a0x + has * b0x;
        s_w[(d0 + 1) * 49 + w] = a0y + has * b0y;
        s_w[(d0 + 64) * 49 + w] = a1x + has * b1x;
        s_w[(d0 + 65) * 49 + w] = a1y + has * b1y;
    }
    __syncthreads();

    // ---- coalesced float4 store of out[b][d][w] ----
    float* obase = out + (size_t)b * DOUT * WIN;
    #pragma unroll
    for (int it = 0; it < 6; it++) {
        int j = it * 1024 + tid * 4;   // 48 % 4 == 0 -> all 4 elems share d
        int d = j / 48;
        int w = j - d * 48;
        const float* src = s_w + d * 49 + w;
        float4 v = make_float4(src[0], src[1], src[2], src[3]);
        *reinterpret_cast<float4*>(obase + j) = v;
    }
}

// ---------------------------------------------------------------------------
extern "C" void kernel_launch(void* const* d_in, const int* in_sizes, int n_in,
                              void* d_out, int out_size) {
    const float* input = (const float*)d_in[0];
    const float* Wm    = (const float*)d_in[1];
    const float* bias  = (const float*)d_in[2];

    const int* bi;
    const int* wi;
    int n_events;
    if (n_in >= 6 && in_sizes[3] == 1) {
        bi = (const int*)d_in[4];
        wi = (const int*)d_in[5];
        n_events = in_sizes[4];
    } else {
        bi = (const int*)d_in[3];
        wi = (const int*)d_in[4];
        n_events = in_sizes[3];
    }

    int eb = (n_events + 255) / 256;

    zero_cnt_kernel<<<(NSEG + 255) / 256, 256>>>();
    hist_kernel<<<eb, 256>>>(bi, wi, n_events);
    scan_a_kernel<<<SCAN_NBLK, 1024>>>();
    scan_c_kernel<<<NSEG / 256, 256>>>();
    scatter_idx_kernel<<<eb, 256>>>(bi, wi, n_events);
    reduce_kernel<<<NSEG / 8, 256>>>(input);
    pool_gemm_kernel<<<BATCH, 256>>>(Wm, bias, (float*)d_out);
}